// round 12
// baseline (speedup 1.0000x reference)
#include <cuda_runtime.h>
#include <cstdint>
#include <cstddef>

#define B_     128
#define T_     32
#define NCAT   32
#define MAXCH  80
#define BM     64
#define BN     128
#define BK     32
#define NT     128

// SMEM layout (bytes, per CTA):
//  [0, 2*16896)            B fp32 stage, NS=2, [k 0..31][n 0..127] stride 132 words
//  [33792, 33792+2*5120)   A f16 stage,  NS=2, [row 0..63][kpair 0..15] stride 20 words
//  [44032, 44032+8448)     B f16 packed, NS=1, [kp 0..15][n 0..127] stride 132 words
#define BP32_BYTES 16896
#define A16_BYTES  5120
#define A16_OFF    (2 * BP32_BYTES)
#define BF16_OFF   (A16_OFF + 2 * A16_BYTES)
#define SMEM_REQ   (BF16_OFF + 8448)             // 52480

__device__ unsigned short g_x16[B_ * T_ * 1536];     // 12.6 MB f16 input
__device__ unsigned short g_hidden16[B_ * T_ * 1024]; // 8 MB f16 hidden

__device__ __forceinline__ uint32_t smem_u32(const void* p) {
    uint32_t a;
    asm("{ .reg .u64 t; cvta.to.shared.u64 t, %1; cvt.u32.u64 %0, t; }" : "=r"(a) : "l"(p));
    return a;
}
__device__ __forceinline__ void cpa16(uint32_t d, const void* s) {
    asm volatile("cp.async.cg.shared.global [%0], [%1], 16;" :: "r"(d), "l"(s));
}
// pack {lo=f16(lo), hi=f16(hi)} -- first PTX source goes to the HIGH half
__device__ __forceinline__ uint32_t packh2(float lo, float hi) {
    uint32_t r;
    asm("cvt.rn.f16x2.f32 %0, %1, %2;" : "=r"(r) : "f"(hi), "f"(lo));
    return r;
}

// ---------------------------------------------------------------------------
// x fp32 -> f16 pre-convert (6.29M elems, float4 per thread)
// ---------------------------------------------------------------------------
__global__ void cvt_x_kernel(const float4* __restrict__ x4) {
    int i = blockIdx.x * 256 + threadIdx.x;
    float4 v = x4[i];
    uint2 r;
    r.x = packh2(v.x, v.y);
    r.y = packh2(v.z, v.w);
    ((uint2*)g_x16)[i] = r;
}

// ---------------------------------------------------------------------------
// One layer: out[chunk 64 rows x 128 n-tile] = act(A[64,K] @ W[cat][K,1024] + b)
// A consumed as f16 (global f16), B converted fp32->f16 once per tile in smem.
// 128 threads = 4 warps (2M x 2N), warp tile 32x64, mma.m16n8k16.f16, 4 CTAs/SM.
// ---------------------------------------------------------------------------
template <int K, bool RELU, bool IN_HID, bool OUT_HID>
__global__ __launch_bounds__(NT, 4)
void catmlp_gemm(const float* __restrict__ Wt, const float* __restrict__ bias,
                 const int* __restrict__ cat_ids, float* __restrict__ gout)
{
    extern __shared__ char smem[];
    const uint32_t sb = smem_u32(smem);

    __shared__ int cats[B_];
    __shared__ int s_cnt[NCAT], s_base[NCAT];
    __shared__ int s_cb[2], s_cat, s_nch;
    __shared__ const char* rowp[BM];

    const int tid  = threadIdx.x;
    const int wid  = tid >> 5;
    const int lane = tid & 31;
    const int bx   = blockIdx.x;

    // ---- per-CTA chunk decomposition (groups of <=2 same-cat batches) ----
    cats[tid] = cat_ids[tid];
    __syncthreads();
    if (wid == 0) {
        int n = 0;
        #pragma unroll 4
        for (int b = 0; b < B_; b++) n += (cats[b] == lane);
        int ch = (n + 1) >> 1;
        int inc = ch;
        #pragma unroll
        for (int d = 1; d < 32; d <<= 1) {
            int v = __shfl_up_sync(0xffffffffu, inc, d);
            if (lane >= d) inc += v;
        }
        s_cnt[lane]  = n;
        s_base[lane] = inc - ch;
        if (lane == 31) s_nch = inc;
        bool own = (bx >= inc - ch) && (bx < inc);
        uint32_t m = __ballot_sync(0xffffffffu, own);
        if (lane == 0) s_cat = m ? (__ffs(m) - 1) : 0;
    }
    __syncthreads();
    if (bx >= s_nch) return;

    const int cat = s_cat;
    const int jg  = bx - s_base[cat];
    const int ncc = s_cnt[cat];
    if (cats[tid] == cat) {
        int r = 0;
        for (int b = 0; b < tid; b++) r += (cats[b] == cat);
        int nv = ncc - jg * 2;
        if (nv > 2) nv = 2;
        if (r >= jg * 2 && r < jg * 2 + 2) s_cb[r - jg * 2] = tid;
        if (r == ncc - 1)
            for (int q = nv; q < 2; q++) s_cb[q] = tid;  // pad by replication
    }
    __syncthreads();

    const unsigned short* in16 = IN_HID ? g_hidden16 : g_x16;
    if (tid < BM) {
        int b = s_cb[tid >> 5];
        rowp[tid] = (const char*)(in16 + ((size_t)b * T_ + (tid & 31)) * (size_t)K);
    }
    const float* Wc = Wt + (size_t)cat * K * 1024;
    const int n0 = blockIdx.y * BN;
    __syncthreads();

    constexpr int NC = K / BK;

    auto stage = [&](int ch) {
        const int k0 = ch * BK;
        const uint32_t b32 = sb + (ch & 1) * BP32_BYTES;
        #pragma unroll
        for (int j = 0; j < 8; j++) {             // B fp32: 1024 x 16B / 128 thr
            int c  = tid + (j << 7);
            int k  = c >> 5;
            int nw = (c & 31) << 2;
            cpa16(b32 + (k * 132 + nw) * 4, Wc + (size_t)(k0 + k) * 1024 + n0 + nw);
        }
        const uint32_t ab = sb + A16_OFF + (ch & 1) * A16_BYTES;
        #pragma unroll
        for (int j = 0; j < 2; j++) {             // A f16: 256 x 16B / 128 thr
            int c   = tid + (j << 7);
            int row = c >> 2;
            int g   = c & 3;
            cpa16(ab + row * 80 + g * 16, rowp[row] + 2 * k0 + 16 * g);
        }
        asm volatile("cp.async.commit_group;" ::: "memory");
    };

    stage(0);
    stage(1);

    const int wm = (wid & 1) * 32;               // 0 / 32 (M warp)
    const int wn = (wid >> 1) * 64;              // 0 / 64 (N warp)
    const int lg = lane >> 2;
    const int lr = lane & 3;

    float acc[2][8][4];
    #pragma unroll
    for (int mf = 0; mf < 2; mf++)
        #pragma unroll
        for (int nf = 0; nf < 8; nf++)
            #pragma unroll
            for (int q = 0; q < 4; q++) acc[mf][nf][q] = 0.f;

    uint32_t* const Bp = (uint32_t*)(smem + BF16_OFF);

    for (int i = 0; i < NC; i++) {
        if (i < NC - 1) asm volatile("cp.async.wait_group 1;" ::: "memory");
        else            asm volatile("cp.async.wait_group 0;" ::: "memory");
        __syncthreads();                          // stage i ready; f16B free

        // ---- convert B tile fp32 -> packed f16x2 [kp][n], once per element ----
        {
            const float* Bs32 = (const float*)(smem + (size_t)(i & 1) * BP32_BYTES);
            const int n = tid;                    // 0..127, conflict-free columns
            #pragma unroll
            for (int kp = 0; kp < 16; kp++) {
                float f0 = Bs32[(2 * kp    ) * 132 + n];
                float f1 = Bs32[(2 * kp + 1) * 132 + n];
                Bp[kp * 132 + n] = packh2(f0, f1);
            }
        }
        __syncthreads();                          // f16B ready

        const uint32_t* As16 = (const uint32_t*)(smem + A16_OFF + (size_t)(i & 1) * A16_BYTES);

        #pragma unroll
        for (int ks = 0; ks < 2; ks++) {          // two K=16 steps per chunk
            const int c0 = (ks << 3) + lr;        // kpair col
            uint32_t ua[2][4];
            #pragma unroll
            for (int mf = 0; mf < 2; mf++) {
                const int r0 = wm + mf * 16 + lg;
                ua[mf][0] = As16[(r0    ) * 20 + c0];
                ua[mf][1] = As16[(r0 + 8) * 20 + c0];
                ua[mf][2] = As16[(r0    ) * 20 + c0 + 4];
                ua[mf][3] = As16[(r0 + 8) * 20 + c0 + 4];
            }
            uint32_t ub[8][2];
            const int kp0 = (ks << 3) + lr;
            const int nb  = wn + lg;
            #pragma unroll
            for (int nf = 0; nf < 8; nf++) {
                ub[nf][0] = Bp[(kp0    ) * 132 + nb + nf * 8];
                ub[nf][1] = Bp[(kp0 + 4) * 132 + nb + nf * 8];
            }
            #pragma unroll
            for (int mf = 0; mf < 2; mf++)
                #pragma unroll
                for (int nf = 0; nf < 8; nf++)
                    asm volatile(
                        "mma.sync.aligned.m16n8k16.row.col.f32.f16.f16.f32 "
                        "{%0,%1,%2,%3}, {%4,%5,%6,%7}, {%8,%9}, {%0,%1,%2,%3};"
                        : "+f"(acc[mf][nf][0]), "+f"(acc[mf][nf][1]),
                          "+f"(acc[mf][nf][2]), "+f"(acc[mf][nf][3])
                        : "r"(ua[mf][0]), "r"(ua[mf][1]), "r"(ua[mf][2]), "r"(ua[mf][3]),
                          "r"(ub[nf][0]), "r"(ub[nf][1]));
        }

        __syncthreads();                          // MMA done with A[i&1], fp32B[i&1]
        if (i + 2 < NC) stage(i + 2);             // refill; overlaps next convert/MMA
    }

    // ---- epilogue ----
    const float* brow = bias + (size_t)cat * 1024 + n0;
    float2 bb[8];
    #pragma unroll
    for (int nf = 0; nf < 8; nf++)
        bb[nf] = *(const float2*)(brow + wn + nf * 8 + lr * 2);

    const int batch = s_cb[wid & 1];              // warp tile = one 32-row slab
    #pragma unroll
    for (int mf = 0; mf < 2; mf++) {
        const int r0 = mf * 16 + lg;              // row within slab
        #pragma unroll
        for (int nf = 0; nf < 8; nf++) {
            const int col = wn + nf * 8 + lr * 2;
            float v0x = acc[mf][nf][0] + bb[nf].x;
            float v0y = acc[mf][nf][1] + bb[nf].y;
            float v1x = acc[mf][nf][2] + bb[nf].x;
            float v1y = acc[mf][nf][3] + bb[nf].y;
            if (RELU) {
                v0x = fmaxf(v0x, 0.f); v0y = fmaxf(v0y, 0.f);
                v1x = fmaxf(v1x, 0.f); v1y = fmaxf(v1y, 0.f);
            }
            if (OUT_HID) {                        // packed f16 hidden store
                uint32_t* o16 = (uint32_t*)g_hidden16;
                size_t w0 = (((size_t)batch * T_ + r0    ) * 1024 + n0 + col) >> 1;
                size_t w1 = (((size_t)batch * T_ + r0 + 8) * 1024 + n0 + col) >> 1;
                o16[w0] = packh2(v0x, v0y);
                o16[w1] = packh2(v1x, v1y);
            } else {                              // fp32 output
                float* o0 = gout + ((size_t)batch * T_ + r0    ) * 1024 + n0 + col;
                float* o1 = gout + ((size_t)batch * T_ + r0 + 8) * 1024 + n0 + col;
                *(float2*)o0 = make_float2(v0x, v0y);
                *(float2*)o1 = make_float2(v1x, v1y);
            }
        }
    }
}

// ---------------------------------------------------------------------------
extern "C" void kernel_launch(void* const* d_in, const int* in_sizes, int n_in,
                              void* d_out, int out_size) {
    const float* x   = (const float*)d_in[0];
    const int*   cat = (const int*)  d_in[1];
    const float* W1  = (const float*)d_in[2];
    const float* b1  = (const float*)d_in[3];
    const float* W2  = (const float*)d_in[4];
    const float* b2  = (const float*)d_in[5];
    float*       out = (float*)d_out;

    cudaFuncSetAttribute(catmlp_gemm<1536, true,  false, true >,
                         cudaFuncAttributeMaxDynamicSharedMemorySize, SMEM_REQ);
    cudaFuncSetAttribute(catmlp_gemm<1024, false, true,  false>,
                         cudaFuncAttributeMaxDynamicSharedMemorySize, SMEM_REQ);

    cvt_x_kernel<<<(B_ * T_ * 1536) / (256 * 4), 256>>>((const float4*)x);

    dim3 grid(MAXCH, 1024 / BN);
    catmlp_gemm<1536, true,  false, true ><<<grid, NT, SMEM_REQ>>>(W1, b1, cat, nullptr);
    catmlp_gemm<1024, false, true,  false><<<grid, NT, SMEM_REQ>>>(W2, b2, cat, out);
}

// round 13
// speedup vs baseline: 1.1190x; 1.1190x over previous
#include <cuda_runtime.h>
#include <cstdint>
#include <cstddef>

#define B_     128
#define T_     32
#define NCAT   32
#define MAXCH  80
#define BM     64
#define BN     128
#define BK     32
#define NT     128

// SMEM (bytes): [0, 3*8704) B f16 tiles (16 kp x 136 w), [26112, +2*5120) A f16
#define BSTR       136
#define BF16_BYTES (16 * BSTR * 4)               // 8704
#define A16_OFF    (3 * BF16_BYTES)              // 26112
#define A16_BYTES  (64 * 80)                     // 5120
#define SMEM_REQ   (A16_OFF + 2 * A16_BYTES)     // 36352

__device__ unsigned short g_x16[B_ * T_ * 1536];      // f16 input
__device__ unsigned short g_hidden16[B_ * T_ * 1024]; // f16 hidden

__device__ __forceinline__ uint32_t smem_u32(const void* p) {
    uint32_t a;
    asm("{ .reg .u64 t; cvta.to.shared.u64 t, %1; cvt.u32.u64 %0, t; }" : "=r"(a) : "l"(p));
    return a;
}
__device__ __forceinline__ void cpa16(uint32_t d, const void* s) {
    asm volatile("cp.async.cg.shared.global [%0], [%1], 16;" :: "r"(d), "l"(s));
}
// pack {lo=f16(lo), hi=f16(hi)} -- first PTX source is the HIGH half
__device__ __forceinline__ uint32_t packh2(float lo, float hi) {
    uint32_t r;
    asm("cvt.rn.f16x2.f32 %0, %1, %2;" : "=r"(r) : "f"(hi), "f"(lo));
    return r;
}

__global__ void cvt_x_kernel(const float4* __restrict__ x4) {
    int i = blockIdx.x * 256 + threadIdx.x;
    float4 v = x4[i];
    uint2 r;
    r.x = packh2(v.x, v.y);
    r.y = packh2(v.z, v.w);
    ((uint2*)g_x16)[i] = r;
}

// ---------------------------------------------------------------------------
// out[chunk 64 rows x 128 n] = act(A[64,K] @ W[cat][K,1024] + b)
// A: f16 via cp.async (pre-converted). B: fp32 LDG -> f16 pack -> STS at stage
// time, two chunks ahead, NS=3. 4 warps (2Mx2N), warp tile 32x64,
// mma.m16n8k16.f16, 4 CTAs/SM.
// ---------------------------------------------------------------------------
template <int K, bool RELU, bool IN_HID, bool OUT_HID>
__global__ __launch_bounds__(NT, 4)
void catmlp_gemm(const float* __restrict__ Wt, const float* __restrict__ bias,
                 const int* __restrict__ cat_ids, float* __restrict__ gout)
{
    extern __shared__ char smem[];
    const uint32_t sb = smem_u32(smem);

    __shared__ int cats[B_];
    __shared__ int s_cnt[NCAT], s_base[NCAT];
    __shared__ int s_cb[2], s_cat, s_nch;
    __shared__ const char* rowp[BM];

    const int tid  = threadIdx.x;
    const int wid  = tid >> 5;
    const int lane = tid & 31;
    const int bx   = blockIdx.x;

    // ---- per-CTA chunk decomposition (groups of <=2 same-cat batches) ----
    cats[tid] = cat_ids[tid];
    __syncthreads();
    if (wid == 0) {
        int n = 0;
        #pragma unroll 4
        for (int b = 0; b < B_; b++) n += (cats[b] == lane);
        int ch = (n + 1) >> 1;
        int inc = ch;
        #pragma unroll
        for (int d = 1; d < 32; d <<= 1) {
            int v = __shfl_up_sync(0xffffffffu, inc, d);
            if (lane >= d) inc += v;
        }
        s_cnt[lane]  = n;
        s_base[lane] = inc - ch;
        if (lane == 31) s_nch = inc;
        bool own = (bx >= inc - ch) && (bx < inc);
        uint32_t m = __ballot_sync(0xffffffffu, own);
        if (lane == 0) s_cat = m ? (__ffs(m) - 1) : 0;
    }
    __syncthreads();
    if (bx >= s_nch) return;

    const int cat = s_cat;
    const int jg  = bx - s_base[cat];
    const int ncc = s_cnt[cat];
    if (cats[tid] == cat) {
        int r = 0;
        for (int b = 0; b < tid; b++) r += (cats[b] == cat);
        int nv = ncc - jg * 2;
        if (nv > 2) nv = 2;
        if (r >= jg * 2 && r < jg * 2 + 2) s_cb[r - jg * 2] = tid;
        if (r == ncc - 1)
            for (int q = nv; q < 2; q++) s_cb[q] = tid;  // pad by replication
    }
    __syncthreads();

    const unsigned short* in16 = IN_HID ? g_hidden16 : g_x16;
    if (tid < BM) {
        int b = s_cb[tid >> 5];
        rowp[tid] = (const char*)(in16 + ((size_t)b * T_ + (tid & 31)) * (size_t)K);
    }
    const float* Wc = Wt + (size_t)cat * K * 1024;
    const int n0 = blockIdx.y * BN;
    __syncthreads();

    constexpr int NC = K / BK;

    auto stageA = [&](int ch) {
        const uint32_t ab = sb + A16_OFF + (ch & 1) * A16_BYTES;
        const int k2 = 2 * ch * BK;               // byte offset = k0 elems * 2
        #pragma unroll
        for (int j = 0; j < 2; j++) {
            int c   = tid + (j << 7);
            int row = c >> 2;
            int g   = c & 3;
            cpa16(ab + row * 80 + g * 16, rowp[row] + k2 + 16 * g);
        }
        asm volatile("cp.async.commit_group;" ::: "memory");
    };

    // full-chunk B convert (prologue): LDG fp32 -> pack -> STS f16 tile
    auto convB = [&](int ch) {
        const int k0 = ch * BK;
        uint32_t* Bp = (uint32_t*)(smem + (ch % 3) * BF16_BYTES);
        #pragma unroll
        for (int j = 0; j < 4; j++) {
            int q  = tid + (j << 7);
            int kp = q >> 5, qn = q & 31;
            const float* s = Wc + (size_t)(k0 + 2 * kp) * 1024 + n0 + 4 * qn;
            float4 v0 = *(const float4*)s;
            float4 v1 = *(const float4*)(s + 1024);
            uint4 w;
            w.x = packh2(v0.x, v1.x); w.y = packh2(v0.y, v1.y);
            w.z = packh2(v0.z, v1.z); w.w = packh2(v0.w, v1.w);
            *(uint4*)(Bp + kp * BSTR + 4 * qn) = w;
        }
    };

    stageA(0);
    stageA(1);
    convB(0);
    convB(1);

    const int wm = (wid & 1) * 32;               // 0 / 32 (M warp)
    const int wn = (wid >> 1) * 64;              // 0 / 64 (N warp)
    const int lg = lane >> 2;
    const int lr = lane & 3;

    float acc[2][8][4];
    #pragma unroll
    for (int mf = 0; mf < 2; mf++)
        #pragma unroll
        for (int nf = 0; nf < 8; nf++)
            #pragma unroll
            for (int q = 0; q < 4; q++) acc[mf][nf][q] = 0.f;

    for (int i = 0; i < NC; i++) {
        if (i < NC - 1) asm volatile("cp.async.wait_group 1;" ::: "memory");
        else            asm volatile("cp.async.wait_group 0;" ::: "memory");
        __syncthreads();

        const uint32_t* As16 = (const uint32_t*)(smem + A16_OFF + (size_t)(i & 1) * A16_BYTES);
        const uint32_t* Bp   = (const uint32_t*)(smem + (size_t)(i % 3) * BF16_BYTES);

        const bool pf = (i + 2 < NC);
        const int k2 = (i + 2) * BK;
        uint32_t* Bp2 = (uint32_t*)(smem + (size_t)((i + 2) % 3) * BF16_BYTES);
        float4 h[2][2];

        // -- prefetch wave 0 (quads j=0,1) for chunk i+2 --
        if (pf) {
            #pragma unroll
            for (int j = 0; j < 2; j++) {
                int q  = tid + (j << 7);
                int kp = q >> 5, qn = q & 31;
                const float* s = Wc + (size_t)(k2 + 2 * kp) * 1024 + n0 + 4 * qn;
                h[j][0] = *(const float4*)s;
                h[j][1] = *(const float4*)(s + 1024);
            }
        }

        // -- compute ks = 0 --
        #pragma unroll
        for (int ks = 0; ks < 2; ks++) {
            const int c0 = (ks << 3) + lr;        // kpair col
            uint32_t ua[2][4];
            #pragma unroll
            for (int mf = 0; mf < 2; mf++) {
                const int r0 = wm + mf * 16 + lg;
                ua[mf][0] = As16[(r0    ) * 20 + c0];
                ua[mf][1] = As16[(r0 + 8) * 20 + c0];
                ua[mf][2] = As16[(r0    ) * 20 + c0 + 4];
                ua[mf][3] = As16[(r0 + 8) * 20 + c0 + 4];
            }
            uint32_t ub[8][2];
            const int nb = wn + lg;
            #pragma unroll
            for (int nf = 0; nf < 8; nf++) {
                ub[nf][0] = Bp[(c0    ) * BSTR + nb + nf * 8];
                ub[nf][1] = Bp[(c0 + 4) * BSTR + nb + nf * 8];
            }
            #pragma unroll
            for (int mf = 0; mf < 2; mf++)
                #pragma unroll
                for (int nf = 0; nf < 8; nf++)
                    asm volatile(
                        "mma.sync.aligned.m16n8k16.row.col.f32.f16.f16.f32 "
                        "{%0,%1,%2,%3}, {%4,%5,%6,%7}, {%8,%9}, {%0,%1,%2,%3};"
                        : "+f"(acc[mf][nf][0]), "+f"(acc[mf][nf][1]),
                          "+f"(acc[mf][nf][2]), "+f"(acc[mf][nf][3])
                        : "r"(ua[mf][0]), "r"(ua[mf][1]), "r"(ua[mf][2]), "r"(ua[mf][3]),
                          "r"(ub[nf][0]), "r"(ub[nf][1]));

            // between the two ks steps: drain wave 0, launch wave 1
            if (ks == 0 && pf) {
                #pragma unroll
                for (int j = 0; j < 2; j++) {
                    int q  = tid + (j << 7);
                    int kp = q >> 5, qn = q & 31;
                    uint4 w;
                    w.x = packh2(h[j][0].x, h[j][1].x);
                    w.y = packh2(h[j][0].y, h[j][1].y);
                    w.z = packh2(h[j][0].z, h[j][1].z);
                    w.w = packh2(h[j][0].w, h[j][1].w);
                    *(uint4*)(Bp2 + kp * BSTR + 4 * qn) = w;
                }
                #pragma unroll
                for (int j = 0; j < 2; j++) {
                    int q  = tid + ((j + 2) << 7);
                    int kp = q >> 5, qn = q & 31;
                    const float* s = Wc + (size_t)(k2 + 2 * kp) * 1024 + n0 + 4 * qn;
                    h[j][0] = *(const float4*)s;
                    h[j][1] = *(const float4*)(s + 1024);
                }
            }
        }

        // -- drain wave 1 --
        if (pf) {
            #pragma unroll
            for (int j = 0; j < 2; j++) {
                int q  = tid + ((j + 2) << 7);
                int kp = q >> 5, qn = q & 31;
                uint4 w;
                w.x = packh2(h[j][0].x, h[j][1].x);
                w.y = packh2(h[j][0].y, h[j][1].y);
                w.z = packh2(h[j][0].z, h[j][1].z);
                w.w = packh2(h[j][0].w, h[j][1].w);
                *(uint4*)(Bp2 + kp * BSTR + 4 * qn) = w;
            }
        }

        __syncthreads();                          // done reading A16[i&1], B[i%3]
        if (pf) stageA(i + 2);                    // refill A (cp.async)
    }

    // ---- epilogue ----
    const float* brow = bias + (size_t)cat * 1024 + n0;
    float2 bb[8];
    #pragma unroll
    for (int nf = 0; nf < 8; nf++)
        bb[nf] = *(const float2*)(brow + wn + nf * 8 + lr * 2);

    const int batch = s_cb[wid & 1];              // warp tile = one 32-row slab
    #pragma unroll
    for (int mf = 0; mf < 2; mf++) {
        const int r0 = mf * 16 + lg;
        #pragma unroll
        for (int nf = 0; nf < 8; nf++) {
            const int col = wn + nf * 8 + lr * 2;
            float v0x = acc[mf][nf][0] + bb[nf].x;
            float v0y = acc[mf][nf][1] + bb[nf].y;
            float v1x = acc[mf][nf][2] + bb[nf].x;
            float v1y = acc[mf][nf][3] + bb[nf].y;
            if (RELU) {
                v0x = fmaxf(v0x, 0.f); v0y = fmaxf(v0y, 0.f);
                v1x = fmaxf(v1x, 0.f); v1y = fmaxf(v1y, 0.f);
            }
            if (OUT_HID) {                        // packed f16 hidden store
                uint32_t* o16 = (uint32_t*)g_hidden16;
                size_t w0 = (((size_t)batch * T_ + r0    ) * 1024 + n0 + col) >> 1;
                size_t w1 = (((size_t)batch * T_ + r0 + 8) * 1024 + n0 + col) >> 1;
                o16[w0] = packh2(v0x, v0y);
                o16[w1] = packh2(v1x, v1y);
            } else {
                float* o0 = gout + ((size_t)batch * T_ + r0    ) * 1024 + n0 + col;
                float* o1 = gout + ((size_t)batch * T_ + r0 + 8) * 1024 + n0 + col;
                *(float2*)o0 = make_float2(v0x, v0y);
                *(float2*)o1 = make_float2(v1x, v1y);
            }
        }
    }
}

// ---------------------------------------------------------------------------
extern "C" void kernel_launch(void* const* d_in, const int* in_sizes, int n_in,
                              void* d_out, int out_size) {
    const float* x   = (const float*)d_in[0];
    const int*   cat = (const int*)  d_in[1];
    const float* W1  = (const float*)d_in[2];
    const float* b1  = (const float*)d_in[3];
    const float* W2  = (const float*)d_in[4];
    const float* b2  = (const float*)d_in[5];
    float*       out = (float*)d_out;

    cudaFuncSetAttribute(catmlp_gemm<1536, true,  false, true >,
                         cudaFuncAttributeMaxDynamicSharedMemorySize, SMEM_REQ);
    cudaFuncSetAttribute(catmlp_gemm<1024, false, true,  false>,
                         cudaFuncAttributeMaxDynamicSharedMemorySize, SMEM_REQ);

    cvt_x_kernel<<<(B_ * T_ * 1536) / (256 * 4), 256>>>((const float4*)x);

    dim3 grid(MAXCH, 1024 / BN);
    catmlp_gemm<1536, true,  false, true ><<<grid, NT, SMEM_REQ>>>(W1, b1, cat, nullptr);
    catmlp_gemm<1024, false, true,  false><<<grid, NT, SMEM_REQ>>>(W2, b2, cat, out);
}

// round 14
// speedup vs baseline: 1.1393x; 1.0181x over previous
#include <cuda_runtime.h>
#include <cstdint>
#include <cstddef>

#define B_     128
#define T_     32
#define NCAT   32
#define MAXCH  80
#define BM     64
#define BN     128
#define BK     32
#define NT     128

// SMEM (bytes): [0, 3*8704) B f16 tiles (16 kp x 136 w); [26112, +3*5120) A f16
#define BSTR       136
#define BF16_BYTES (16 * BSTR * 4)               // 8704
#define A16_OFF    (3 * BF16_BYTES)              // 26112
#define A16_BYTES  (64 * 80)                     // 5120
#define SMEM_REQ   (A16_OFF + 3 * A16_BYTES)     // 41472

__device__ unsigned short g_x16[B_ * T_ * 1536];      // f16 input
__device__ unsigned short g_hidden16[B_ * T_ * 1024]; // f16 hidden

__device__ __forceinline__ uint32_t smem_u32(const void* p) {
    uint32_t a;
    asm("{ .reg .u64 t; cvta.to.shared.u64 t, %1; cvt.u32.u64 %0, t; }" : "=r"(a) : "l"(p));
    return a;
}
__device__ __forceinline__ void cpa16(uint32_t d, const void* s) {
    asm volatile("cp.async.cg.shared.global [%0], [%1], 16;" :: "r"(d), "l"(s));
}
// pack {lo=f16(lo), hi=f16(hi)} -- first PTX source is the HIGH half
__device__ __forceinline__ uint32_t packh2(float lo, float hi) {
    uint32_t r;
    asm("cvt.rn.f16x2.f32 %0, %1, %2;" : "=r"(r) : "f"(hi), "f"(lo));
    return r;
}

__global__ void cvt_x_kernel(const float4* __restrict__ x4) {
    int i = blockIdx.x * 256 + threadIdx.x;
    float4 v = x4[i];
    uint2 r;
    r.x = packh2(v.x, v.y);
    r.y = packh2(v.z, v.w);
    ((uint2*)g_x16)[i] = r;
}

// ---------------------------------------------------------------------------
// out[chunk 64 rows x 128 n] = act(A[64,K] @ W[cat][K,1024] + b)
// A: f16 cp.async NS=3. B: fp32 LDG -> f16 pack -> STS two chunks ahead, NS=3.
// ONE __syncthreads per mainloop iteration (CUTLASS multistage ordering).
// 4 warps (2Mx2N), warp tile 32x64, mma.m16n8k16.f16, 4 CTAs/SM.
// ---------------------------------------------------------------------------
template <int K, bool RELU, bool IN_HID, bool OUT_HID>
__global__ __launch_bounds__(NT, 4)
void catmlp_gemm(const float* __restrict__ Wt, const float* __restrict__ bias,
                 const int* __restrict__ cat_ids, float* __restrict__ gout)
{
    extern __shared__ char smem[];
    const uint32_t sb = smem_u32(smem);

    __shared__ int cats[B_];
    __shared__ int s_cnt[NCAT], s_base[NCAT];
    __shared__ int s_cb[2], s_cat, s_nch;
    __shared__ const char* rowp[BM];

    const int tid  = threadIdx.x;
    const int wid  = tid >> 5;
    const int lane = tid & 31;
    const int bx   = blockIdx.x;

    // ---- per-CTA chunk decomposition (groups of <=2 same-cat batches) ----
    cats[tid] = cat_ids[tid];
    __syncthreads();
    if (wid == 0) {
        int n = 0;
        #pragma unroll 4
        for (int b = 0; b < B_; b++) n += (cats[b] == lane);
        int ch = (n + 1) >> 1;
        int inc = ch;
        #pragma unroll
        for (int d = 1; d < 32; d <<= 1) {
            int v = __shfl_up_sync(0xffffffffu, inc, d);
            if (lane >= d) inc += v;
        }
        s_cnt[lane]  = n;
        s_base[lane] = inc - ch;
        if (lane == 31) s_nch = inc;
        bool own = (bx >= inc - ch) && (bx < inc);
        uint32_t m = __ballot_sync(0xffffffffu, own);
        if (lane == 0) s_cat = m ? (__ffs(m) - 1) : 0;
    }
    __syncthreads();
    if (bx >= s_nch) return;

    const int cat = s_cat;
    const int jg  = bx - s_base[cat];
    const int ncc = s_cnt[cat];
    if (cats[tid] == cat) {
        int r = 0;
        for (int b = 0; b < tid; b++) r += (cats[b] == cat);
        int nv = ncc - jg * 2;
        if (nv > 2) nv = 2;
        if (r >= jg * 2 && r < jg * 2 + 2) s_cb[r - jg * 2] = tid;
        if (r == ncc - 1)
            for (int q = nv; q < 2; q++) s_cb[q] = tid;  // pad by replication
    }
    __syncthreads();

    const unsigned short* in16 = IN_HID ? g_hidden16 : g_x16;
    if (tid < BM) {
        int b = s_cb[tid >> 5];
        rowp[tid] = (const char*)(in16 + ((size_t)b * T_ + (tid & 31)) * (size_t)K);
    }
    const float* Wc = Wt + (size_t)cat * K * 1024;
    const int n0 = blockIdx.y * BN;
    __syncthreads();

    constexpr int NC = K / BK;

    auto stageA = [&](int ch) {
        const uint32_t ab = sb + A16_OFF + (ch % 3) * A16_BYTES;
        const int k2 = 2 * ch * BK;               // byte offset = k0 elems * 2
        #pragma unroll
        for (int j = 0; j < 2; j++) {
            int c   = tid + (j << 7);
            int row = c >> 2;
            int g   = c & 3;
            cpa16(ab + row * 80 + g * 16, rowp[row] + k2 + 16 * g);
        }
        asm volatile("cp.async.commit_group;" ::: "memory");
    };

    // full-chunk B convert (prologue only): LDG fp32 -> pack -> STS f16 tile
    auto convB = [&](int ch) {
        const int k0 = ch * BK;
        uint32_t* Bp = (uint32_t*)(smem + (ch % 3) * BF16_BYTES);
        #pragma unroll
        for (int j = 0; j < 4; j++) {
            int q  = tid + (j << 7);
            int kp = q >> 5, qn = q & 31;
            const float* s = Wc + (size_t)(k0 + 2 * kp) * 1024 + n0 + 4 * qn;
            float4 v0 = *(const float4*)s;
            float4 v1 = *(const float4*)(s + 1024);
            uint4 w;
            w.x = packh2(v0.x, v1.x); w.y = packh2(v0.y, v1.y);
            w.z = packh2(v0.z, v1.z); w.w = packh2(v0.w, v1.w);
            *(uint4*)(Bp + kp * BSTR + 4 * qn) = w;
        }
    };

    stageA(0);
    stageA(1);
    convB(0);
    convB(1);

    const int wm = (wid & 1) * 32;               // 0 / 32 (M warp)
    const int wn = (wid >> 1) * 64;              // 0 / 64 (N warp)
    const int lg = lane >> 2;
    const int lr = lane & 3;

    float acc[2][8][4];
    #pragma unroll
    for (int mf = 0; mf < 2; mf++)
        #pragma unroll
        for (int nf = 0; nf < 8; nf++)
            #pragma unroll
            for (int q = 0; q < 4; q++) acc[mf][nf][q] = 0.f;

    for (int i = 0; i < NC; i++) {
        if (i < NC - 1) asm volatile("cp.async.wait_group 1;" ::: "memory");
        else            asm volatile("cp.async.wait_group 0;" ::: "memory");
        __syncthreads();                          // ONE barrier per iteration

        const uint32_t* As16 = (const uint32_t*)(smem + A16_OFF + (size_t)(i % 3) * A16_BYTES);
        const uint32_t* Bp   = (const uint32_t*)(smem + (size_t)(i % 3) * BF16_BYTES);

        const bool pf = (i + 2 < NC);
        const int k2 = (i + 2) * BK;
        uint32_t* Bp2 = (uint32_t*)(smem + (size_t)((i + 2) % 3) * BF16_BYTES);
        float4 h[2][2];

        // -- prefetch wave 0 (quads j=0,1) of B chunk i+2 --
        if (pf) {
            #pragma unroll
            for (int j = 0; j < 2; j++) {
                int q  = tid + (j << 7);
                int kp = q >> 5, qn = q & 31;
                const float* s = Wc + (size_t)(k2 + 2 * kp) * 1024 + n0 + 4 * qn;
                h[j][0] = *(const float4*)s;
                h[j][1] = *(const float4*)(s + 1024);
            }
        }

        #pragma unroll
        for (int ks = 0; ks < 2; ks++) {
            const int c0 = (ks << 3) + lr;        // kpair col
            uint32_t ua[2][4];
            #pragma unroll
            for (int mf = 0; mf < 2; mf++) {
                const int r0 = wm + mf * 16 + lg;
                ua[mf][0] = As16[(r0    ) * 20 + c0];
                ua[mf][1] = As16[(r0 + 8) * 20 + c0];
                ua[mf][2] = As16[(r0    ) * 20 + c0 + 4];
                ua[mf][3] = As16[(r0 + 8) * 20 + c0 + 4];
            }
            uint32_t ub[8][2];
            const int nb = wn + lg;
            #pragma unroll
            for (int nf = 0; nf < 8; nf++) {
                ub[nf][0] = Bp[(c0    ) * BSTR + nb + nf * 8];
                ub[nf][1] = Bp[(c0 + 4) * BSTR + nb + nf * 8];
            }
            #pragma unroll
            for (int mf = 0; mf < 2; mf++)
                #pragma unroll
                for (int nf = 0; nf < 8; nf++)
                    asm volatile(
                        "mma.sync.aligned.m16n8k16.row.col.f32.f16.f16.f32 "
                        "{%0,%1,%2,%3}, {%4,%5,%6,%7}, {%8,%9}, {%0,%1,%2,%3};"
                        : "+f"(acc[mf][nf][0]), "+f"(acc[mf][nf][1]),
                          "+f"(acc[mf][nf][2]), "+f"(acc[mf][nf][3])
                        : "r"(ua[mf][0]), "r"(ua[mf][1]), "r"(ua[mf][2]), "r"(ua[mf][3]),
                          "r"(ub[nf][0]), "r"(ub[nf][1]));

            // between ks steps: drain wave 0, launch wave 1 (chunk i+2)
            if (ks == 0 && pf) {
                #pragma unroll
                for (int j = 0; j < 2; j++) {
                    int q  = tid + (j << 7);
                    int kp = q >> 5, qn = q & 31;
                    uint4 w;
                    w.x = packh2(h[j][0].x, h[j][1].x);
                    w.y = packh2(h[j][0].y, h[j][1].y);
                    w.z = packh2(h[j][0].z, h[j][1].z);
                    w.w = packh2(h[j][0].w, h[j][1].w);
                    *(uint4*)(Bp2 + kp * BSTR + 4 * qn) = w;
                }
                #pragma unroll
                for (int j = 0; j < 2; j++) {
                    int q  = tid + ((j + 2) << 7);
                    int kp = q >> 5, qn = q & 31;
                    const float* s = Wc + (size_t)(k2 + 2 * kp) * 1024 + n0 + 4 * qn;
                    h[j][0] = *(const float4*)s;
                    h[j][1] = *(const float4*)(s + 1024);
                }
            }
        }

        // -- drain wave 1 of B chunk i+2 --
        if (pf) {
            #pragma unroll
            for (int j = 0; j < 2; j++) {
                int q  = tid + ((j + 2) << 7);
                int kp = q >> 5, qn = q & 31;
                uint4 w;
                w.x = packh2(h[j][0].x, h[j][1].x);
                w.y = packh2(h[j][0].y, h[j][1].y);
                w.z = packh2(h[j][0].z, h[j][1].z);
                w.w = packh2(h[j][0].w, h[j][1].w);
                *(uint4*)(Bp2 + kp * BSTR + 4 * qn) = w;
            }
            stageA(i + 2);                        // cp.async refill, no barrier
        }
    }

    // ---- epilogue ----
    const float* brow = bias + (size_t)cat * 1024 + n0;
    float2 bb[8];
    #pragma unroll
    for (int nf = 0; nf < 8; nf++)
        bb[nf] = *(const float2*)(brow + wn + nf * 8 + lr * 2);

    const int batch = s_cb[wid & 1];              // warp tile = one 32-row slab
    #pragma unroll
    for (int mf = 0; mf < 2; mf++) {
        const int r0 = mf * 16 + lg;
        #pragma unroll
        for (int nf = 0; nf < 8; nf++) {
            const int col = wn + nf * 8 + lr * 2;
            float v0x = acc[mf][nf][0] + bb[nf].x;
            float v0y = acc[mf][nf][1] + bb[nf].y;
            float v1x = acc[mf][nf][2] + bb[nf].x;
            float v1y = acc[mf][nf][3] + bb[nf].y;
            if (RELU) {
                v0x = fmaxf(v0x, 0.f); v0y = fmaxf(v0y, 0.f);
                v1x = fmaxf(v1x, 0.f); v1y = fmaxf(v1y, 0.f);
            }
            if (OUT_HID) {                        // packed f16 hidden store
                uint32_t* o16 = (uint32_t*)g_hidden16;
                size_t w0 = (((size_t)batch * T_ + r0    ) * 1024 + n0 + col) >> 1;
                size_t w1 = (((size_t)batch * T_ + r0 + 8) * 1024 + n0 + col) >> 1;
                o16[w0] = packh2(v0x, v0y);
                o16[w1] = packh2(v1x, v1y);
            } else {
                float* o0 = gout + ((size_t)batch * T_ + r0    ) * 1024 + n0 + col;
                float* o1 = gout + ((size_t)batch * T_ + r0 + 8) * 1024 + n0 + col;
                *(float2*)o0 = make_float2(v0x, v0y);
                *(float2*)o1 = make_float2(v1x, v1y);
            }
        }
    }
}

// ---------------------------------------------------------------------------
extern "C" void kernel_launch(void* const* d_in, const int* in_sizes, int n_in,
                              void* d_out, int out_size) {
    const float* x   = (const float*)d_in[0];
    const int*   cat = (const int*)  d_in[1];
    const float* W1  = (const float*)d_in[2];
    const float* b1  = (const float*)d_in[3];
    const float* W2  = (const float*)d_in[4];
    const float* b2  = (const float*)d_in[5];
    float*       out = (float*)d_out;

    cudaFuncSetAttribute(catmlp_gemm<1536, true,  false, true >,
                         cudaFuncAttributeMaxDynamicSharedMemorySize, SMEM_REQ);
    cudaFuncSetAttribute(catmlp_gemm<1024, false, true,  false>,
                         cudaFuncAttributeMaxDynamicSharedMemorySize, SMEM_REQ);

    cvt_x_kernel<<<(B_ * T_ * 1536) / (256 * 4), 256>>>((const float4*)x);

    dim3 grid(MAXCH, 1024 / BN);
    catmlp_gemm<1536, true,  false, true ><<<grid, NT, SMEM_REQ>>>(W1, b1, cat, nullptr);
    catmlp_gemm<1024, false, true,  false><<<grid, NT, SMEM_REQ>>>(W2, b2, cat, out);
}